// round 2
// baseline (speedup 1.0000x reference)
#include <cuda_runtime.h>
#include <cuda_bf16.h>
#include <cstdint>

// ---------------- problem constants ----------------
// x: [32, 3136, 512]; windows 7x7 -> 2048 windows * 49 tokens
#define BATCH   32
#define HW      56
#define CDIM    512
#define WSZ     7
#define NWSIDE  8            // 56/7
#define NWIN    2048         // 32*8*8
#define TTOK    49
#define MTOT    (NWIN * TTOK)   // 100352
#define NQKV    1536
#define NHEAD   8
#define HD      64

// ---------------- scratch (device globals; no allocs allowed) -------------
// qkv in window-row layout: part p (q/k/v), row m = w*49+t, col cc = h*64+d
__device__ float g_qkv[3ULL * MTOT * CDIM];     // 616 MB
// attention output, already laid out as the reference's reshape(-1,49,512):
// offset = w*25088 + h*3136 + t*64 + d
__device__ float g_att[(size_t)MTOT * CDIM];    // 205 MB

// map windowed row m -> source/dest row in [B*3136)
__device__ __forceinline__ int win_row_map(int m) {
    int w = m / TTOK, t = m - w * TTOK;
    int b = w >> 6;
    int wi = (w >> 3) & 7;
    int wj = w & 7;
    int r = t / WSZ, c = t - r * WSZ;
    return (b * HW + wi * WSZ + r) * HW + wj * WSZ + c;
}

// ---------------- GEMM 1: QKV = gather(x) @ w_qkv + b_qkv ----------------
// M=100352, K=512, N=1536. 64x64 tile, BK=16, 256 threads, 4x4 microtile.
__global__ void qkv_gemm(const float* __restrict__ x,
                         const float* __restrict__ w,
                         const float* __restrict__ bias) {
    __shared__ float As[64][17];
    __shared__ float Bs[16][68];

    const int bm = blockIdx.x * 64;
    const int bn = blockIdx.y * 64;
    const int tid = threadIdx.x;
    const int tx = tid & 15, ty = tid >> 4;

    // A loader: row = tid/4 (0..63), k quad = (tid%4)*4
    const int arow = tid >> 2;
    const int akq  = (tid & 3) * 4;
    const int asrc = win_row_map(bm + arow);
    const float* aptr = x + (size_t)asrc * CDIM + akq;

    // B loader: k row = tid/16 (0..15), n quad = (tid%16)*4
    const int bkrow = tid >> 4;
    const int bnq   = (tid & 15) * 4;
    const float* bptr = w + (size_t)bkrow * NQKV + bn + bnq;

    float acc[4][4] = {};

    for (int k0 = 0; k0 < CDIM; k0 += 16) {
        float4 av = *(const float4*)(aptr + k0);
        As[arow][akq + 0] = av.x;
        As[arow][akq + 1] = av.y;
        As[arow][akq + 2] = av.z;
        As[arow][akq + 3] = av.w;
        float4 bv = *(const float4*)(bptr + (size_t)k0 * NQKV);
        Bs[bkrow][bnq + 0] = bv.x;
        Bs[bkrow][bnq + 1] = bv.y;
        Bs[bkrow][bnq + 2] = bv.z;
        Bs[bkrow][bnq + 3] = bv.w;
        __syncthreads();
#pragma unroll
        for (int kk = 0; kk < 16; kk++) {
            float ra[4], rb[4];
#pragma unroll
            for (int i = 0; i < 4; i++) ra[i] = As[ty * 4 + i][kk];
#pragma unroll
            for (int j = 0; j < 4; j++) rb[j] = Bs[kk][tx * 4 + j];
#pragma unroll
            for (int i = 0; i < 4; i++)
#pragma unroll
                for (int j = 0; j < 4; j++) acc[i][j] = fmaf(ra[i], rb[j], acc[i][j]);
        }
        __syncthreads();
    }

    // epilogue: add bias, scatter into q/k/v parts of g_qkv
    const int row0 = bm + ty * 4;
    const int col0 = bn + tx * 4;
#pragma unroll
    for (int i = 0; i < 4; i++) {
        const int m = row0 + i;
#pragma unroll
        for (int j = 0; j < 4; j++) {
            const int n = col0 + j;
            const float v = acc[i][j] + bias[n];
            const int p  = n >> 9;       // 0=q,1=k,2=v
            const int cc = n & 511;
            g_qkv[(size_t)p * MTOT * CDIM + (size_t)m * CDIM + cc] = v;
        }
    }
}

// ---------------- attention: per (window, token) 8x8 head-attention --------
// unit = w*49+t. S[h][g] = sum_d q[h,d]k[g,d] / 8; softmax over g; O = P V.
// 256 threads per block, 4 units per block, 64 threads per unit.
__global__ void attn_kernel() {
    __shared__ float qs[4][512];
    __shared__ float ks[4][512];
    __shared__ float vs[4][512];
    __shared__ float ps[4][64];

    const int tid = threadIdx.x;
    const int u   = tid >> 6;        // sub-unit 0..3
    const int lt  = tid & 63;        // thread within unit
    const int unit = blockIdx.x * 4 + u;   // < MTOT (exact: 100352/4 = 25088)

    const size_t rowoff = (size_t)unit * CDIM;
    const float* qrow = g_qkv + rowoff;
    const float* krow = g_qkv + (size_t)MTOT * CDIM + rowoff;
    const float* vrow = g_qkv + 2ULL * MTOT * CDIM + rowoff;

#pragma unroll
    for (int i = lt; i < 512; i += 64) {
        qs[u][i] = qrow[i];
        ks[u][i] = krow[i];
        vs[u][i] = vrow[i];
    }
    __syncthreads();

    const int h = lt >> 3, g = lt & 7;
    float s = 0.f;
#pragma unroll
    for (int d = 0; d < 64; d++) s = fmaf(qs[u][h * 64 + d], ks[u][g * 64 + d], s);
    s *= 0.125f;   // hd^-0.5 = 1/8

    // softmax over g: groups of 8 lanes (aligned within warp)
    float mx = s;
#pragma unroll
    for (int off = 4; off >= 1; off >>= 1)
        mx = fmaxf(mx, __shfl_xor_sync(0xffffffffu, mx, off));
    float e = __expf(s - mx);
    float sum = e;
#pragma unroll
    for (int off = 4; off >= 1; off >>= 1)
        sum += __shfl_xor_sync(0xffffffffu, sum, off);
    ps[u][lt] = e / sum;
    __syncthreads();

    // O[h][d] for d in [g*8, g*8+8)
    const int w = unit / TTOK, t = unit - w * TTOK;
    float* obase = g_att + (size_t)w * (TTOK * CDIM) + (size_t)h * (TTOK * HD) + (size_t)t * HD;
    const int d0 = g * 8;
#pragma unroll
    for (int i = 0; i < 8; i++) {
        const int d = d0 + i;
        float o = 0.f;
#pragma unroll
        for (int gg = 0; gg < 8; gg++)
            o = fmaf(ps[u][h * 8 + gg], vs[u][gg * 64 + d], o);
        obase[d] = o;
    }
}

// ---------------- GEMM 2: out = g_att @ w_proj + b_proj, scatter rows -----
__global__ void proj_gemm(const float* __restrict__ w,
                          const float* __restrict__ bias,
                          float* __restrict__ out) {
    __shared__ float As[64][17];
    __shared__ float Bs[16][68];

    const int bm = blockIdx.x * 64;
    const int bn = blockIdx.y * 64;
    const int tid = threadIdx.x;
    const int tx = tid & 15, ty = tid >> 4;

    const int arow = tid >> 2;
    const int akq  = (tid & 3) * 4;
    const float* aptr = g_att + (size_t)(bm + arow) * CDIM + akq;

    const int bkrow = tid >> 4;
    const int bnq   = (tid & 15) * 4;
    const float* bptr = w + (size_t)bkrow * CDIM + bn + bnq;

    float acc[4][4] = {};

    for (int k0 = 0; k0 < CDIM; k0 += 16) {
        float4 av = *(const float4*)(aptr + k0);
        As[arow][akq + 0] = av.x;
        As[arow][akq + 1] = av.y;
        As[arow][akq + 2] = av.z;
        As[arow][akq + 3] = av.w;
        float4 bv = *(const float4*)(bptr + (size_t)k0 * CDIM);
        Bs[bkrow][bnq + 0] = bv.x;
        Bs[bkrow][bnq + 1] = bv.y;
        Bs[bkrow][bnq + 2] = bv.z;
        Bs[bkrow][bnq + 3] = bv.w;
        __syncthreads();
#pragma unroll
        for (int kk = 0; kk < 16; kk++) {
            float ra[4], rb[4];
#pragma unroll
            for (int i = 0; i < 4; i++) ra[i] = As[ty * 4 + i][kk];
#pragma unroll
            for (int j = 0; j < 4; j++) rb[j] = Bs[kk][tx * 4 + j];
#pragma unroll
            for (int i = 0; i < 4; i++)
#pragma unroll
                for (int j = 0; j < 4; j++) acc[i][j] = fmaf(ra[i], rb[j], acc[i][j]);
        }
        __syncthreads();
    }

    const int row0 = bm + ty * 4;
    const int col0 = bn + tx * 4;
#pragma unroll
    for (int i = 0; i < 4; i++) {
        const int dst = win_row_map(row0 + i);
#pragma unroll
        for (int j = 0; j < 4; j++) {
            const int n = col0 + j;
            out[(size_t)dst * CDIM + n] = acc[i][j] + bias[n];
        }
    }
}

// ---------------- launch ----------------
extern "C" void kernel_launch(void* const* d_in, const int* in_sizes, int n_in,
                              void* d_out, int out_size) {
    const float* x      = (const float*)d_in[0];
    const float* w_qkv  = (const float*)d_in[1];
    const float* b_qkv  = (const float*)d_in[2];
    const float* w_proj = (const float*)d_in[3];
    const float* b_proj = (const float*)d_in[4];
    float* out = (float*)d_out;

    {
        dim3 grid(MTOT / 64, NQKV / 64);
        qkv_gemm<<<grid, 256>>>(x, w_qkv, b_qkv);
    }
    {
        attn_kernel<<<MTOT / 4, 256>>>();
    }
    {
        dim3 grid(MTOT / 64, CDIM / 64);
        proj_gemm<<<grid, 256>>>(w_proj, b_proj, out);
    }
}

// round 6
// speedup vs baseline: 2.0332x; 2.0332x over previous
#include <cuda_runtime.h>
#include <cuda_bf16.h>
#include <cstdint>

// ---------------- problem constants ----------------
#define BATCH   32
#define HW      56
#define CDIM    512
#define WSZ     7
#define NWIN    2048         // 32*8*8
#define TTOK    49
#define MTOT    (NWIN * TTOK)   // 100352
#define NQKV    1536
#define NHEAD   8
#define HD      64

// GEMM tiling
#define BM 128
#define BN 128
#define BK 16

// ---------------- scratch (device globals; no allocs allowed) -------------
__device__ float g_qkv[3ULL * MTOT * CDIM];     // q/k/v parts
// attention output in reference reshape(-1,49,512) layout:
// offset = w*25088 + h*3136 + t*64 + d
__device__ float g_att[(size_t)MTOT * CDIM];

// map windowed row m -> source/dest row in [B*3136)
__device__ __forceinline__ int win_row_map(int m) {
    int w = m / TTOK, t = m - w * TTOK;
    int b = w >> 6;
    int wi = (w >> 3) & 7;
    int wj = w & 7;
    int r = t / WSZ, c = t - r * WSZ;
    return (b * HW + wi * WSZ + r) * HW + wj * WSZ + c;
}

__device__ __forceinline__ uint32_t f2tf32(float f) {
    uint32_t u;
    asm("cvt.rna.tf32.f32 %0, %1;" : "=r"(u) : "f"(f));
    return u;
}

// ---------------- tf32 mma GEMM -------------------------------------------
// C[M x NDIM] = A[M x 512] @ W[512 x NDIM] + bias
// MODE 0: A = x (rows gathered via win_row_map), output scattered into g_qkv
// MODE 1: A = g_att (device global, linear rows), output scattered via
//         win_row_map into out
template<int NDIM, int MODE>
__global__ __launch_bounds__(256) void mma_gemm(
    const float* __restrict__ A,
    const float* __restrict__ W,
    const float* __restrict__ bias,
    float* __restrict__ out)
{
    __shared__ uint32_t As[2][BM][BK + 4];    // stride 20: conflict-free frag reads
    __shared__ uint32_t Bs[2][BK][BN + 8];    // stride 136: conflict-free frag reads

    const int tid = threadIdx.x;
    const int lane = tid & 31;
    const int wid  = tid >> 5;
    const int warp_m = wid >> 2;   // 0..1  (64 rows)
    const int warp_n = wid & 3;    // 0..3  (32 cols)
    const int bm = blockIdx.x * BM;
    const int bn = blockIdx.y * BN;

    // A source: MODE 1 reads the device-global scratch (param A unused).
    const float* Abase = (MODE == 1) ? (const float*)g_att : A;

    // A loader: row = tid>>1 (0..127), col quad = (tid&1)*8
    const int arow = tid >> 1;
    const int acq  = (tid & 1) * 8;
    const float* aptr;
    if (MODE == 0) aptr = Abase + (size_t)win_row_map(bm + arow) * CDIM + acq;
    else           aptr = Abase + (size_t)(bm + arow) * CDIM + acq;

    // B loader: k row = tid>>4 (0..15), col = (tid&15)*8
    const int bkr = tid >> 4;
    const int bcq = (tid & 15) * 8;
    const float* bptr = W + (size_t)bkr * NDIM + bn + bcq;

    float acc[4][4][4] = {};

    // prologue: stage 0
    {
        float4 a0 = *(const float4*)(aptr);
        float4 a1 = *(const float4*)(aptr + 4);
        As[0][arow][acq + 0] = f2tf32(a0.x);
        As[0][arow][acq + 1] = f2tf32(a0.y);
        As[0][arow][acq + 2] = f2tf32(a0.z);
        As[0][arow][acq + 3] = f2tf32(a0.w);
        As[0][arow][acq + 4] = f2tf32(a1.x);
        As[0][arow][acq + 5] = f2tf32(a1.y);
        As[0][arow][acq + 6] = f2tf32(a1.z);
        As[0][arow][acq + 7] = f2tf32(a1.w);
        float4 b0 = *(const float4*)(bptr);
        float4 b1 = *(const float4*)(bptr + 4);
        Bs[0][bkr][bcq + 0] = f2tf32(b0.x);
        Bs[0][bkr][bcq + 1] = f2tf32(b0.y);
        Bs[0][bkr][bcq + 2] = f2tf32(b0.z);
        Bs[0][bkr][bcq + 3] = f2tf32(b0.w);
        Bs[0][bkr][bcq + 4] = f2tf32(b1.x);
        Bs[0][bkr][bcq + 5] = f2tf32(b1.y);
        Bs[0][bkr][bcq + 6] = f2tf32(b1.z);
        Bs[0][bkr][bcq + 7] = f2tf32(b1.w);
    }
    __syncthreads();

    const int NIT = CDIM / BK;   // 32
    int s = 0;
    float aReg[8], bReg[8];

#pragma unroll 1
    for (int it = 0; it < NIT; ++it) {
        // prefetch next tile (global -> regs)
        if (it + 1 < NIT) {
            const float* ap = aptr + (it + 1) * BK;
            float4 a0 = *(const float4*)(ap);
            float4 a1 = *(const float4*)(ap + 4);
            aReg[0] = a0.x; aReg[1] = a0.y; aReg[2] = a0.z; aReg[3] = a0.w;
            aReg[4] = a1.x; aReg[5] = a1.y; aReg[6] = a1.z; aReg[7] = a1.w;
            const float* bp = bptr + (size_t)(it + 1) * BK * NDIM;
            float4 b0 = *(const float4*)(bp);
            float4 b1 = *(const float4*)(bp + 4);
            bReg[0] = b0.x; bReg[1] = b0.y; bReg[2] = b0.z; bReg[3] = b0.w;
            bReg[4] = b1.x; bReg[5] = b1.y; bReg[6] = b1.z; bReg[7] = b1.w;
        }

        // compute: 2 k-steps of 8
#pragma unroll
        for (int ks = 0; ks < 2; ks++) {
            const int k = ks * 8;
            uint32_t af[4][4];
#pragma unroll
            for (int mt = 0; mt < 4; mt++) {
                const int r = warp_m * 64 + mt * 16 + (lane >> 2);
                const int c = k + (lane & 3);
                af[mt][0] = As[s][r][c];
                af[mt][1] = As[s][r + 8][c];
                af[mt][2] = As[s][r][c + 4];
                af[mt][3] = As[s][r + 8][c + 4];
            }
            uint32_t bf[4][2];
#pragma unroll
            for (int nt = 0; nt < 4; nt++) {
                const int cc = warp_n * 32 + nt * 8 + (lane >> 2);
                const int rr = k + (lane & 3);
                bf[nt][0] = Bs[s][rr][cc];
                bf[nt][1] = Bs[s][rr + 4][cc];
            }
#pragma unroll
            for (int mt = 0; mt < 4; mt++)
#pragma unroll
                for (int nt = 0; nt < 4; nt++)
                    asm volatile(
                        "mma.sync.aligned.m16n8k8.row.col.f32.tf32.tf32.f32 "
                        "{%0,%1,%2,%3},{%4,%5,%6,%7},{%8,%9},{%0,%1,%2,%3};"
                        : "+f"(acc[mt][nt][0]), "+f"(acc[mt][nt][1]),
                          "+f"(acc[mt][nt][2]), "+f"(acc[mt][nt][3])
                        : "r"(af[mt][0]), "r"(af[mt][1]), "r"(af[mt][2]), "r"(af[mt][3]),
                          "r"(bf[nt][0]), "r"(bf[nt][1]));
        }

        // write prefetched tile into the other stage
        if (it + 1 < NIT) {
            const int ns = s ^ 1;
            As[ns][arow][acq + 0] = f2tf32(aReg[0]);
            As[ns][arow][acq + 1] = f2tf32(aReg[1]);
            As[ns][arow][acq + 2] = f2tf32(aReg[2]);
            As[ns][arow][acq + 3] = f2tf32(aReg[3]);
            As[ns][arow][acq + 4] = f2tf32(aReg[4]);
            As[ns][arow][acq + 5] = f2tf32(aReg[5]);
            As[ns][arow][acq + 6] = f2tf32(aReg[6]);
            As[ns][arow][acq + 7] = f2tf32(aReg[7]);
            Bs[ns][bkr][bcq + 0] = f2tf32(bReg[0]);
            Bs[ns][bkr][bcq + 1] = f2tf32(bReg[1]);
            Bs[ns][bkr][bcq + 2] = f2tf32(bReg[2]);
            Bs[ns][bkr][bcq + 3] = f2tf32(bReg[3]);
            Bs[ns][bkr][bcq + 4] = f2tf32(bReg[4]);
            Bs[ns][bkr][bcq + 5] = f2tf32(bReg[5]);
            Bs[ns][bkr][bcq + 6] = f2tf32(bReg[6]);
            Bs[ns][bkr][bcq + 7] = f2tf32(bReg[7]);
            __syncthreads();
            s = ns;
        }
    }

    // ---------------- epilogue ----------------
#pragma unroll
    for (int mt = 0; mt < 4; mt++) {
        const int row0 = bm + warp_m * 64 + mt * 16 + (lane >> 2);
#pragma unroll
        for (int half = 0; half < 2; half++) {
            const int m = row0 + half * 8;
            int dst = 0;
            if (MODE == 1) dst = win_row_map(m);
#pragma unroll
            for (int nt = 0; nt < 4; nt++) {
                const int col0 = bn + warp_n * 32 + nt * 8 + 2 * (lane & 3);
#pragma unroll
                for (int j = 0; j < 2; j++) {
                    const int n = col0 + j;
                    const float v = acc[mt][nt][half * 2 + j] + bias[n];
                    if (MODE == 0) {
                        const int p  = n >> 9;      // 0=q,1=k,2=v
                        const int cc = n & 511;
                        g_qkv[(size_t)p * MTOT * CDIM + (size_t)m * CDIM + cc] = v;
                    } else {
                        out[(size_t)dst * CDIM + n] = v;
                    }
                }
            }
        }
    }
}

// ---------------- attention: per (window, token) 8x8 head-attention --------
__global__ void attn_kernel() {
    __shared__ float qs[4][512];
    __shared__ float ks[4][512];
    __shared__ float vs[4][512];
    __shared__ float ps[4][64];

    const int tid = threadIdx.x;
    const int u   = tid >> 6;
    const int lt  = tid & 63;
    const int unit = blockIdx.x * 4 + u;

    const size_t rowoff = (size_t)unit * CDIM;
    const float* qrow = g_qkv + rowoff;
    const float* krow = g_qkv + (size_t)MTOT * CDIM + rowoff;
    const float* vrow = g_qkv + 2ULL * MTOT * CDIM + rowoff;

#pragma unroll
    for (int i = lt; i < 512; i += 64) {
        qs[u][i] = qrow[i];
        ks[u][i] = krow[i];
        vs[u][i] = vrow[i];
    }
    __syncthreads();

    const int h = lt >> 3, g = lt & 7;
    float s = 0.f;
#pragma unroll
    for (int d = 0; d < 64; d++) s = fmaf(qs[u][h * 64 + d], ks[u][g * 64 + d], s);
    s *= 0.125f;

    float mx = s;
#pragma unroll
    for (int off = 4; off >= 1; off >>= 1)
        mx = fmaxf(mx, __shfl_xor_sync(0xffffffffu, mx, off));
    float e = __expf(s - mx);
    float sum = e;
#pragma unroll
    for (int off = 4; off >= 1; off >>= 1)
        sum += __shfl_xor_sync(0xffffffffu, sum, off);
    ps[u][lt] = e / sum;
    __syncthreads();

    const int w = unit / TTOK, t = unit - w * TTOK;
    float* obase = g_att + (size_t)w * (TTOK * CDIM) + (size_t)h * (TTOK * HD) + (size_t)t * HD;
    const int d0 = g * 8;
#pragma unroll
    for (int i = 0; i < 8; i++) {
        const int d = d0 + i;
        float o = 0.f;
#pragma unroll
        for (int gg = 0; gg < 8; gg++)
            o = fmaf(ps[u][h * 8 + gg], vs[u][gg * 64 + d], o);
        obase[d] = o;
    }
}

// ---------------- launch ----------------
extern "C" void kernel_launch(void* const* d_in, const int* in_sizes, int n_in,
                              void* d_out, int out_size) {
    const float* x      = (const float*)d_in[0];
    const float* w_qkv  = (const float*)d_in[1];
    const float* b_qkv  = (const float*)d_in[2];
    const float* w_proj = (const float*)d_in[3];
    const float* b_proj = (const float*)d_in[4];
    float* out = (float*)d_out;

    {
        dim3 grid(MTOT / BM, NQKV / BN);   // 784 x 12
        mma_gemm<NQKV, 0><<<grid, 256>>>(x, w_qkv, b_qkv, nullptr);
    }
    {
        attn_kernel<<<MTOT / 4, 256>>>();
    }
    {
        dim3 grid(MTOT / BM, CDIM / BN);   // 784 x 4
        mma_gemm<CDIM, 1><<<grid, 256>>>(nullptr, w_proj, b_proj, out);
    }
}

// round 7
// speedup vs baseline: 2.6915x; 1.3237x over previous
#include <cuda_runtime.h>
#include <cuda_bf16.h>
#include <cstdint>

// ---------------- problem constants ----------------
#define BATCH   32
#define HW      56
#define CDIM    512
#define WSZ     7
#define NWIN    2048         // 32*8*8
#define TTOK    49
#define MTOT    (NWIN * TTOK)   // 100352
#define NQKV    1536
#define NHEAD   8
#define HD      64

// GEMM tiling
#define BM 128
#define BN 128
#define BK 16
#define STAGES 3

// ---------------- scratch (device globals; no allocs allowed) -------------
__device__ float g_qkv[3ULL * MTOT * CDIM];     // q/k/v parts
// attention output in reference reshape(-1,49,512) layout:
// offset = w*25088 + h*3136 + t*64 + d
__device__ float g_att[(size_t)MTOT * CDIM];

// map windowed row m -> source/dest row in [B*3136)
__device__ __forceinline__ int win_row_map(int m) {
    int w = m / TTOK, t = m - w * TTOK;
    int b = w >> 6;
    int wi = (w >> 3) & 7;
    int wj = w & 7;
    int r = t / WSZ, c = t - r * WSZ;
    return (b * HW + wi * WSZ + r) * HW + wj * WSZ + c;
}

__device__ __forceinline__ uint32_t f2tf32(float f) {
    uint32_t u;
    asm("cvt.rna.tf32.f32 %0, %1;" : "=r"(u) : "f"(f));
    return u;
}

__device__ __forceinline__ void cp_async16(void* smem_dst, const void* gmem_src) {
    uint32_t s = (uint32_t)__cvta_generic_to_shared(smem_dst);
    asm volatile("cp.async.cg.shared.global [%0], [%1], 16;" :: "r"(s), "l"(gmem_src));
}
__device__ __forceinline__ void cp_commit() {
    asm volatile("cp.async.commit_group;");
}
__device__ __forceinline__ void cp_wait1() {
    asm volatile("cp.async.wait_group 1;");
}

// ---------------- tf32 mma GEMM, 3-stage cp.async pipeline ----------------
// C[M x NDIM] = A[M x 512] @ W[512 x NDIM] + bias
// MODE 0: A = x (rows gathered via win_row_map), output scattered into g_qkv
// MODE 1: A = g_att (device global), output scattered via win_row_map to out
template<int NDIM, int MODE>
__global__ __launch_bounds__(256, 2) void mma_gemm(
    const float* __restrict__ A,
    const float* __restrict__ W,
    const float* __restrict__ bias,
    float* __restrict__ out)
{
    __shared__ float As[STAGES][BM][BK + 4];   // stride 20 floats (80B, 16B-aligned)
    __shared__ float Bs[STAGES][BK][BN + 8];   // stride 136 floats (544B, 16B-aligned)

    const int tid = threadIdx.x;
    const int lane = tid & 31;
    const int wid  = tid >> 5;
    const int warp_m = wid >> 2;   // 0..1  (64 rows)
    const int warp_n = wid & 3;    // 0..3  (32 cols)
    const int bm = blockIdx.x * BM;
    const int bn = blockIdx.y * BN;

    const float* Abase = (MODE == 1) ? (const float*)g_att : A;

    // A loader: row = tid>>1 (0..127), col group = (tid&1)*8
    const int arow = tid >> 1;
    const int acq  = (tid & 1) * 8;
    const float* aptr;
    if (MODE == 0) aptr = Abase + (size_t)win_row_map(bm + arow) * CDIM + acq;
    else           aptr = Abase + (size_t)(bm + arow) * CDIM + acq;

    // B loader: k row = tid>>4 (0..15), col = (tid&15)*8
    const int bkr = tid >> 4;
    const int bcq = (tid & 15) * 8;
    const float* bptr = W + (size_t)bkr * NDIM + bn + bcq;

    float acc[4][4][4] = {};

    const int NIT = CDIM / BK;   // 32

    // prologue: stages 0,1
#pragma unroll
    for (int p = 0; p < 2; p++) {
        const float* ap = aptr + p * BK;
        cp_async16(&As[p][arow][acq],     ap);
        cp_async16(&As[p][arow][acq + 4], ap + 4);
        const float* bp = bptr + (size_t)p * BK * NDIM;
        cp_async16(&Bs[p][bkr][bcq],     bp);
        cp_async16(&Bs[p][bkr][bcq + 4], bp + 4);
        cp_commit();
    }
    cp_wait1();
    __syncthreads();

    int s = 0;

#pragma unroll 1
    for (int it = 0; it < NIT; ++it) {
        // compute on stage s
#pragma unroll
        for (int ks = 0; ks < 2; ks++) {
            const int k = ks * 8;
            uint32_t af[4][4];
#pragma unroll
            for (int mt = 0; mt < 4; mt++) {
                const int r = warp_m * 64 + mt * 16 + (lane >> 2);
                const int c = k + (lane & 3);
                af[mt][0] = f2tf32(As[s][r][c]);
                af[mt][1] = f2tf32(As[s][r + 8][c]);
                af[mt][2] = f2tf32(As[s][r][c + 4]);
                af[mt][3] = f2tf32(As[s][r + 8][c + 4]);
            }
            uint32_t bf[4][2];
#pragma unroll
            for (int nt = 0; nt < 4; nt++) {
                const int cc = warp_n * 32 + nt * 8 + (lane >> 2);
                const int rr = k + (lane & 3);
                bf[nt][0] = f2tf32(Bs[s][rr][cc]);
                bf[nt][1] = f2tf32(Bs[s][rr + 4][cc]);
            }
#pragma unroll
            for (int mt = 0; mt < 4; mt++)
#pragma unroll
                for (int nt = 0; nt < 4; nt++)
                    asm volatile(
                        "mma.sync.aligned.m16n8k8.row.col.f32.tf32.tf32.f32 "
                        "{%0,%1,%2,%3},{%4,%5,%6,%7},{%8,%9},{%0,%1,%2,%3};"
                        : "+f"(acc[mt][nt][0]), "+f"(acc[mt][nt][1]),
                          "+f"(acc[mt][nt][2]), "+f"(acc[mt][nt][3])
                        : "r"(af[mt][0]), "r"(af[mt][1]), "r"(af[mt][2]), "r"(af[mt][3]),
                          "r"(bf[nt][0]), "r"(bf[nt][1]));
        }

        // issue load for iteration it+2 into the stage just freed
        if (it + 2 < NIT) {
            const int ls = (s + 2 >= STAGES) ? (s + 2 - STAGES) : (s + 2);
            const float* ap = aptr + (it + 2) * BK;
            cp_async16(&As[ls][arow][acq],     ap);
            cp_async16(&As[ls][arow][acq + 4], ap + 4);
            const float* bp = bptr + (size_t)(it + 2) * BK * NDIM;
            cp_async16(&Bs[ls][bkr][bcq],     bp);
            cp_async16(&Bs[ls][bkr][bcq + 4], bp + 4);
        }
        cp_commit();
        cp_wait1();
        __syncthreads();

        s = (s + 1 >= STAGES) ? 0 : (s + 1);
    }

    // ---------------- epilogue ----------------
#pragma unroll
    for (int mt = 0; mt < 4; mt++) {
        const int row0 = bm + warp_m * 64 + mt * 16 + (lane >> 2);
#pragma unroll
        for (int half = 0; half < 2; half++) {
            const int m = row0 + half * 8;
            int dst = 0;
            if (MODE == 1) dst = win_row_map(m);
#pragma unroll
            for (int nt = 0; nt < 4; nt++) {
                const int col0 = bn + warp_n * 32 + nt * 8 + 2 * (lane & 3);
#pragma unroll
                for (int j = 0; j < 2; j++) {
                    const int n = col0 + j;
                    const float v = acc[mt][nt][half * 2 + j] + bias[n];
                    if (MODE == 0) {
                        const int p  = n >> 9;      // 0=q,1=k,2=v
                        const int cc = n & 511;
                        g_qkv[(size_t)p * MTOT * CDIM + (size_t)m * CDIM + cc] = v;
                    } else {
                        out[(size_t)dst * CDIM + n] = v;
                    }
                }
            }
        }
    }
}

// ---------------- attention: per (window, token) 8x8 head-attention --------
__global__ void attn_kernel() {
    __shared__ float qs[4][512];
    __shared__ float ks[4][512];
    __shared__ float vs[4][512];
    __shared__ float ps[4][64];

    const int tid = threadIdx.x;
    const int u   = tid >> 6;
    const int lt  = tid & 63;
    const int unit = blockIdx.x * 4 + u;

    const size_t rowoff = (size_t)unit * CDIM;
    const float* qrow = g_qkv + rowoff;
    const float* krow = g_qkv + (size_t)MTOT * CDIM + rowoff;
    const float* vrow = g_qkv + 2ULL * MTOT * CDIM + rowoff;

#pragma unroll
    for (int i = lt; i < 512; i += 64) {
        qs[u][i] = qrow[i];
        ks[u][i] = krow[i];
        vs[u][i] = vrow[i];
    }
    __syncthreads();

    const int h = lt >> 3, g = lt & 7;
    float s = 0.f;
#pragma unroll
    for (int d = 0; d < 64; d++) s = fmaf(qs[u][h * 64 + d], ks[u][g * 64 + d], s);
    s *= 0.125f;

    float mx = s;
#pragma unroll
    for (int off = 4; off >= 1; off >>= 1)
        mx = fmaxf(mx, __shfl_xor_sync(0xffffffffu, mx, off));
    float e = __expf(s - mx);
    float sum = e;
#pragma unroll
    for (int off = 4; off >= 1; off >>= 1)
        sum += __shfl_xor_sync(0xffffffffu, sum, off);
    ps[u][lt] = e / sum;
    __syncthreads();

    const int w = unit / TTOK, t = unit - w * TTOK;
    float* obase = g_att + (size_t)w * (TTOK * CDIM) + (size_t)h * (TTOK * HD) + (size_t)t * HD;
    const int d0 = g * 8;
#pragma unroll
    for (int i = 0; i < 8; i++) {
        const int d = d0 + i;
        float o = 0.f;
#pragma unroll
        for (int gg = 0; gg < 8; gg++)
            o = fmaf(ps[u][h * 8 + gg], vs[u][gg * 64 + d], o);
        obase[d] = o;
    }
}

// ---------------- launch ----------------
extern "C" void kernel_launch(void* const* d_in, const int* in_sizes, int n_in,
                              void* d_out, int out_size) {
    const float* x      = (const float*)d_in[0];
    const float* w_qkv  = (const float*)d_in[1];
    const float* b_qkv  = (const float*)d_in[2];
    const float* w_proj = (const float*)d_in[3];
    const float* b_proj = (const float*)d_in[4];
    float* out = (float*)d_out;

    {
        dim3 grid(MTOT / BM, NQKV / BN);   // 784 x 12
        mma_gemm<NQKV, 0><<<grid, 256>>>(x, w_qkv, b_qkv, nullptr);
    }
    {
        attn_kernel<<<MTOT / 4, 256>>>();
    }
    {
        dim3 grid(MTOT / BM, CDIM / BN);   // 784 x 4
        mma_gemm<CDIM, 1><<<grid, 256>>>(nullptr, w_proj, b_proj, out);
    }
}

// round 8
// speedup vs baseline: 2.8953x; 1.0757x over previous
#include <cuda_runtime.h>
#include <cuda_bf16.h>
#include <cstdint>

// ---------------- problem constants ----------------
#define BATCH   32
#define HW      56
#define CDIM    512
#define WSZ     7
#define NWIN    2048         // 32*8*8
#define TTOK    49
#define MTOT    (NWIN * TTOK)   // 100352
#define NQKV    1536
#define NHEAD   8
#define HD      64

// GEMM tiling
#define BM 128
#define BN 128
#define BK 16
#define STAGES 4

// ---------------- scratch (device globals; no allocs allowed) -------------
__device__ float g_qkv[3ULL * MTOT * CDIM];     // q/k/v parts
// attention output in reference reshape(-1,49,512) layout (pre-rounded tf32):
__device__ float g_att[(size_t)MTOT * CDIM];
// tf32-pre-rounded copies of inputs
__device__ float g_xr[(size_t)BATCH * HW * HW * CDIM];   // rounded x
__device__ float g_wq[(size_t)CDIM * NQKV];              // rounded w_qkv
__device__ float g_wp[(size_t)CDIM * CDIM];              // rounded w_proj

// map windowed row m -> source/dest row in [B*3136)
__device__ __forceinline__ int win_row_map(int m) {
    int w = m / TTOK, t = m - w * TTOK;
    int b = w >> 6;
    int wi = (w >> 3) & 7;
    int wj = w & 7;
    int r = t / WSZ, c = t - r * WSZ;
    return (b * HW + wi * WSZ + r) * HW + wj * WSZ + c;
}

__device__ __forceinline__ uint32_t f2tf32(float f) {
    uint32_t u;
    asm("cvt.rna.tf32.f32 %0, %1;" : "=r"(u) : "f"(f));
    return u;
}

__device__ __forceinline__ void cp_async16(void* smem_dst, const void* gmem_src) {
    uint32_t s = (uint32_t)__cvta_generic_to_shared(smem_dst);
    asm volatile("cp.async.cg.shared.global [%0], [%1], 16;" :: "r"(s), "l"(gmem_src));
}
__device__ __forceinline__ void cp_commit() {
    asm volatile("cp.async.commit_group;");
}
__device__ __forceinline__ void cp_wait2() {
    asm volatile("cp.async.wait_group 2;");
}

// ---------------- prep: round-to-nearest-tf32 copy ------------------------
__global__ void round_copy(const float* __restrict__ src, float* __restrict__ dst) {
    const size_t i = ((size_t)blockIdx.x * blockDim.x + threadIdx.x) * 4;
    float4 v = *(const float4*)(src + i);
    uint4 r;
    r.x = f2tf32(v.x);
    r.y = f2tf32(v.y);
    r.z = f2tf32(v.z);
    r.w = f2tf32(v.w);
    *(uint4*)(dst + i) = r;
}

// ---------------- tf32 mma GEMM, 4-stage cp.async pipeline ----------------
// Operands are pre-rounded to tf32-representable fp32, so fragment reads are
// plain LDS (no cvt); hardware truncation is the identity.
// MODE 0: A = g_xr (rows gathered via win_row_map), W = g_wq, out -> g_qkv
// MODE 1: A = g_att (linear), W = g_wp, out scattered via win_row_map
template<int NDIM, int MODE>
__global__ __launch_bounds__(256, 2) void mma_gemm(
    const float* __restrict__ bias,
    float* __restrict__ out)
{
    __shared__ float As[STAGES][BM][BK + 4];   // stride 20 floats
    __shared__ float Bs[STAGES][BK][BN + 8];   // stride 136 floats

    const int tid = threadIdx.x;
    const int lane = tid & 31;
    const int wid  = tid >> 5;
    const int warp_m = wid >> 2;   // 0..1  (64 rows)
    const int warp_n = wid & 3;    // 0..3  (32 cols)
    const int bm = blockIdx.x * BM;
    const int bn = blockIdx.y * BN;

    const float* Abase = (MODE == 1) ? (const float*)g_att : (const float*)g_xr;
    const float* Wbase = (MODE == 1) ? (const float*)g_wp  : (const float*)g_wq;

    // A loader: row = tid>>1 (0..127), col group = (tid&1)*8
    const int arow = tid >> 1;
    const int acq  = (tid & 1) * 8;
    const float* aptr;
    if (MODE == 0) aptr = Abase + (size_t)win_row_map(bm + arow) * CDIM + acq;
    else           aptr = Abase + (size_t)(bm + arow) * CDIM + acq;

    // B loader: k row = tid>>4 (0..15), col = (tid&15)*8
    const int bkr = tid >> 4;
    const int bcq = (tid & 15) * 8;
    const float* bptr = Wbase + (size_t)bkr * NDIM + bn + bcq;

    float acc[4][4][4] = {};

    const int NIT = CDIM / BK;   // 32

    // prologue: stages 0..2
#pragma unroll
    for (int p = 0; p < STAGES - 1; p++) {
        const float* ap = aptr + p * BK;
        cp_async16(&As[p][arow][acq],     ap);
        cp_async16(&As[p][arow][acq + 4], ap + 4);
        const float* bp = bptr + (size_t)p * BK * NDIM;
        cp_async16(&Bs[p][bkr][bcq],     bp);
        cp_async16(&Bs[p][bkr][bcq + 4], bp + 4);
        cp_commit();
    }
    cp_wait2();
    __syncthreads();

    int s = 0;

#pragma unroll 1
    for (int it = 0; it < NIT; ++it) {
        // compute on stage s
#pragma unroll
        for (int ks = 0; ks < 2; ks++) {
            const int k = ks * 8;
            uint32_t af[4][4];
#pragma unroll
            for (int mt = 0; mt < 4; mt++) {
                const int r = warp_m * 64 + mt * 16 + (lane >> 2);
                const int c = k + (lane & 3);
                af[mt][0] = __float_as_uint(As[s][r][c]);
                af[mt][1] = __float_as_uint(As[s][r + 8][c]);
                af[mt][2] = __float_as_uint(As[s][r][c + 4]);
                af[mt][3] = __float_as_uint(As[s][r + 8][c + 4]);
            }
            uint32_t bf[4][2];
#pragma unroll
            for (int nt = 0; nt < 4; nt++) {
                const int cc = warp_n * 32 + nt * 8 + (lane >> 2);
                const int rr = k + (lane & 3);
                bf[nt][0] = __float_as_uint(Bs[s][rr][cc]);
                bf[nt][1] = __float_as_uint(Bs[s][rr + 4][cc]);
            }
#pragma unroll
            for (int mt = 0; mt < 4; mt++)
#pragma unroll
                for (int nt = 0; nt < 4; nt++)
                    asm volatile(
                        "mma.sync.aligned.m16n8k8.row.col.f32.tf32.tf32.f32 "
                        "{%0,%1,%2,%3},{%4,%5,%6,%7},{%8,%9},{%0,%1,%2,%3};"
                        : "+f"(acc[mt][nt][0]), "+f"(acc[mt][nt][1]),
                          "+f"(acc[mt][nt][2]), "+f"(acc[mt][nt][3])
                        : "r"(af[mt][0]), "r"(af[mt][1]), "r"(af[mt][2]), "r"(af[mt][3]),
                          "r"(bf[nt][0]), "r"(bf[nt][1]));
        }

        // issue load for iteration it+STAGES-1 into the stage just freed
        if (it + STAGES - 1 < NIT) {
            const int ls = (s + STAGES - 1 >= STAGES) ? (s - 1) : (s + STAGES - 1);
            const float* ap = aptr + (it + STAGES - 1) * BK;
            cp_async16(&As[ls][arow][acq],     ap);
            cp_async16(&As[ls][arow][acq + 4], ap + 4);
            const float* bp = bptr + (size_t)(it + STAGES - 1) * BK * NDIM;
            cp_async16(&Bs[ls][bkr][bcq],     bp);
            cp_async16(&Bs[ls][bkr][bcq + 4], bp + 4);
        }
        cp_commit();
        cp_wait2();
        __syncthreads();

        s = (s + 1 >= STAGES) ? 0 : (s + 1);
    }

    // ---------------- epilogue ----------------
#pragma unroll
    for (int mt = 0; mt < 4; mt++) {
        const int row0 = bm + warp_m * 64 + mt * 16 + (lane >> 2);
#pragma unroll
        for (int half = 0; half < 2; half++) {
            const int m = row0 + half * 8;
            int dst = 0;
            if (MODE == 1) dst = win_row_map(m);
#pragma unroll
            for (int nt = 0; nt < 4; nt++) {
                const int col0 = bn + warp_n * 32 + nt * 8 + 2 * (lane & 3);
#pragma unroll
                for (int j = 0; j < 2; j++) {
                    const int n = col0 + j;
                    const float v = acc[mt][nt][half * 2 + j] + bias[n];
                    if (MODE == 0) {
                        const int p  = n >> 9;      // 0=q,1=k,2=v
                        const int cc = n & 511;
                        g_qkv[(size_t)p * MTOT * CDIM + (size_t)m * CDIM + cc] = v;
                    } else {
                        out[(size_t)dst * CDIM + n] = v;
                    }
                }
            }
        }
    }
}

// ---------------- attention: per (window, token) 8x8 head-attention --------
__global__ void attn_kernel() {
    __shared__ float qs[4][512];
    __shared__ float ks[4][512];
    __shared__ float vs[4][512];
    __shared__ float ps[4][64];

    const int tid = threadIdx.x;
    const int u   = tid >> 6;
    const int lt  = tid & 63;
    const int unit = blockIdx.x * 4 + u;

    const size_t rowoff = (size_t)unit * CDIM;
    const float* qrow = g_qkv + rowoff;
    const float* krow = g_qkv + (size_t)MTOT * CDIM + rowoff;
    const float* vrow = g_qkv + 2ULL * MTOT * CDIM + rowoff;

#pragma unroll
    for (int i = lt; i < 512; i += 64) {
        qs[u][i] = qrow[i];
        ks[u][i] = krow[i];
        vs[u][i] = vrow[i];
    }
    __syncthreads();

    const int h = lt >> 3, g = lt & 7;
    float s = 0.f;
#pragma unroll
    for (int d = 0; d < 64; d++) s = fmaf(qs[u][h * 64 + d], ks[u][g * 64 + d], s);
    s *= 0.125f;

    float mx = s;
#pragma unroll
    for (int off = 4; off >= 1; off >>= 1)
        mx = fmaxf(mx, __shfl_xor_sync(0xffffffffu, mx, off));
    float e = __expf(s - mx);
    float sum = e;
#pragma unroll
    for (int off = 4; off >= 1; off >>= 1)
        sum += __shfl_xor_sync(0xffffffffu, sum, off);
    ps[u][lt] = e / sum;
    __syncthreads();

    const int w = unit / TTOK, t = unit - w * TTOK;
    float* obase = g_att + (size_t)w * (TTOK * CDIM) + (size_t)h * (TTOK * HD) + (size_t)t * HD;
    const int d0 = g * 8;
#pragma unroll
    for (int i = 0; i < 8; i++) {
        const int d = d0 + i;
        float o = 0.f;
#pragma unroll
        for (int gg = 0; gg < 8; gg++)
            o = fmaf(ps[u][h * 8 + gg], vs[u][gg * 64 + d], o);
        // pre-round to tf32 so the proj GEMM needs no cvt
        obase[d] = __uint_as_float(f2tf32(o));
    }
}

// ---------------- launch ----------------
extern "C" void kernel_launch(void* const* d_in, const int* in_sizes, int n_in,
                              void* d_out, int out_size) {
    const float* x      = (const float*)d_in[0];
    const float* w_qkv  = (const float*)d_in[1];
    const float* b_qkv  = (const float*)d_in[2];
    const float* w_proj = (const float*)d_in[3];
    const float* b_proj = (const float*)d_in[4];
    float* out = (float*)d_out;

    // prep: round inputs to tf32-representable fp32 (idempotent)
    {
        float* xr; cudaGetSymbolAddress((void**)&xr, g_xr);
        float* wq; cudaGetSymbolAddress((void**)&wq, g_wq);
        float* wp; cudaGetSymbolAddress((void**)&wp, g_wp);
        const size_t nx = (size_t)BATCH * HW * HW * CDIM;       // 51,380,224
        round_copy<<<nx / 4 / 256, 256>>>(x, xr);
        round_copy<<<(CDIM * NQKV) / 4 / 256, 256>>>(w_qkv, wq);
        round_copy<<<(CDIM * CDIM) / 4 / 256, 256>>>(w_proj, wp);
    }
    {
        dim3 grid(MTOT / BM, NQKV / BN);   // 784 x 12
        mma_gemm<NQKV, 0><<<grid, 256>>>(b_qkv, nullptr);
    }
    {
        attn_kernel<<<MTOT / 4, 256>>>();
    }
    {
        dim3 grid(MTOT / BM, CDIM / BN);   // 784 x 4
        mma_gemm<CDIM, 1><<<grid, 256>>>(b_proj, out);
    }
}

// round 10
// speedup vs baseline: 2.9003x; 1.0017x over previous
#include <cuda_runtime.h>
#include <cstdint>

// ---------------- problem constants ----------------
#define BATCH   32
#define HW      56
#define CDIM    512
#define WSZ     7
#define NWIN    2048
#define TTOK    49
#define MTOT    (NWIN * TTOK)   // 100352
#define NQKV    1536

// GEMM tiling
#define BM 128
#define BN 128
#define BK 16
#define STAGES 4
#define SPAD 20                 // padded row stride (floats): conflict-free LDSM

// ---------------- scratch (device globals; no allocs allowed) -------------
__device__ float g_qkv[3ULL * MTOT * CDIM];
__device__ float g_att[(size_t)MTOT * CDIM];            // pre-rounded tf32
__device__ float g_xr[(size_t)BATCH * HW * HW * CDIM];  // rounded x
__device__ float g_wqt[(size_t)NQKV * CDIM];            // rounded w_qkv^T [n][k]
__device__ float g_wpt[(size_t)CDIM * CDIM];            // rounded w_proj^T [n][k]

// map windowed row m -> source/dest row in [B*3136)
__device__ __forceinline__ int win_row_map(int m) {
    int w = m / TTOK, t = m - w * TTOK;
    int b = w >> 6;
    int wi = (w >> 3) & 7;
    int wj = w & 7;
    int r = t / WSZ, c = t - r * WSZ;
    return (b * HW + wi * WSZ + r) * HW + wj * WSZ + c;
}

__device__ __forceinline__ uint32_t f2tf32(float f) {
    uint32_t u;
    asm("cvt.rna.tf32.f32 %0, %1;" : "=r"(u) : "f"(f));
    return u;
}

__device__ __forceinline__ void cp_async16(void* smem_dst, const void* gmem_src) {
    uint32_t s = (uint32_t)__cvta_generic_to_shared(smem_dst);
    asm volatile("cp.async.cg.shared.global [%0], [%1], 16;" :: "r"(s), "l"(gmem_src));
}
__device__ __forceinline__ void cp_commit() {
    asm volatile("cp.async.commit_group;");
}
__device__ __forceinline__ void cp_wait2() {
    asm volatile("cp.async.wait_group 2;");
}

__device__ __forceinline__ void ldsm4(uint32_t& r0, uint32_t& r1, uint32_t& r2,
                                      uint32_t& r3, uint32_t addr) {
    asm volatile("ldmatrix.sync.aligned.m8n8.x4.shared.b16 {%0,%1,%2,%3}, [%4];"
                 : "=r"(r0), "=r"(r1), "=r"(r2), "=r"(r3) : "r"(addr));
}

// ---------------- prep kernels ----------------
__global__ void round_copy(const float* __restrict__ src, float* __restrict__ dst) {
    const size_t i = ((size_t)blockIdx.x * blockDim.x + threadIdx.x) * 4;
    float4 v = *(const float4*)(src + i);
    uint4 r;
    r.x = f2tf32(v.x); r.y = f2tf32(v.y); r.z = f2tf32(v.z); r.w = f2tf32(v.w);
    *(uint4*)(dst + i) = r;
}

// src[R][C] -> dst[C][R], rounded to tf32
__global__ void round_transpose(const float* __restrict__ src, float* __restrict__ dst,
                                int R, int C) {
    __shared__ float t[32][33];
    const int bx = blockIdx.x * 32;
    const int by = blockIdx.y * 32;
    const int tx = threadIdx.x;
    for (int i = threadIdx.y; i < 32; i += 8)
        t[i][tx] = src[(size_t)(by + i) * C + bx + tx];
    __syncthreads();
    for (int i = threadIdx.y; i < 32; i += 8)
        dst[(size_t)(bx + i) * R + by + tx] = __uint_as_float(f2tf32(t[tx][i]));
}

// ---------------- tf32 mma GEMM, 4-stage cp.async + ldmatrix --------------
// A smem: [128 m][16 k] (stride 20), B smem: [128 n][16 k] (stride 20).
// Weights come pre-transposed ([n][k]) and pre-rounded, so B loads are
// row-linear and fragments are pure LDSM (no cvt anywhere in the mainloop).
// MODE 0: A = g_xr gathered via win_row_map, W = g_wqt, out -> g_qkv
// MODE 1: A = g_att linear, W = g_wpt, out scattered via win_row_map
template<int NDIM, int MODE>
__global__ __launch_bounds__(256, 2) void mma_gemm(
    const float* __restrict__ bias,
    float* __restrict__ out)
{
    __shared__ __align__(16) float As[STAGES][BM][SPAD];
    __shared__ __align__(16) float Bs[STAGES][BN][SPAD];

    const int tid = threadIdx.x;
    const int lane = tid & 31;
    const int wid  = tid >> 5;
    const int warp_m = wid >> 2;   // 0..1  (64 rows)
    const int warp_n = wid & 3;    // 0..3  (32 cols)
    // grid swap: N-tile is the fast dimension (L2 reuse of A across N-tiles)
    const int bn = blockIdx.x * BN;
    const int bm = blockIdx.y * BM;

    const float* Abase = (MODE == 1) ? (const float*)g_att : (const float*)g_xr;
    const float* Wt    = (MODE == 1) ? (const float*)g_wpt : (const float*)g_wqt;

    // loaders: row = tid>>1 (0..127), 8-float half = (tid&1)*8
    const int srow = tid >> 1;
    const int scq  = (tid & 1) * 8;
    const int agrow = (MODE == 0) ? win_row_map(bm + srow) : (bm + srow);
    const float* aptr = Abase + (size_t)agrow * CDIM + scq;
    const float* bptr = Wt + (size_t)(bn + srow) * CDIM + scq;

    float acc[4][4][4] = {};

    const int NIT = CDIM / BK;   // 32

    // per-lane LDSM base offsets (bytes within a stage)
    // A matrices per mtile: m0: rows r0+(l&7), k..k+3 ; m1: rows r0+8+(l&7) ;
    //                       m2: rows r0+(l&7), k+4..  ; m3: rows r0+8+(l&7), k+4..
    const int a_row_l = warp_m * 64 + ((lane >> 3) & 1) * 8 + (lane & 7);
    const int a_k_l   = (lane >> 4) * 4;
    // B matrices per ntile-pair: m0:(nt0,kg0) m1:(nt0,kg1) m2:(nt1,kg0) m3:(nt1,kg1)
    const int b_row_l = warp_n * 32 + ((lane >> 4) & 1) * 8 + (lane & 7);
    const int b_k_l   = ((lane >> 3) & 1) * 4;

    const uint32_t sA0 = (uint32_t)__cvta_generic_to_shared(&As[0][0][0]);
    const uint32_t sB0 = (uint32_t)__cvta_generic_to_shared(&Bs[0][0][0]);
    const uint32_t stageB = BM * SPAD * 4;   // bytes per stage

    // prologue: stages 0..2
#pragma unroll
    for (int p = 0; p < STAGES - 1; p++) {
        const float* ap = aptr + p * BK;
        cp_async16(&As[p][srow][scq],     ap);
        cp_async16(&As[p][srow][scq + 4], ap + 4);
        const float* bp = bptr + p * BK;
        cp_async16(&Bs[p][srow][scq],     bp);
        cp_async16(&Bs[p][srow][scq + 4], bp + 4);
        cp_commit();
    }
    cp_wait2();
    __syncthreads();

    int s = 0;

#pragma unroll 1
    for (int it = 0; it < NIT; ++it) {
        // compute on stage s
#pragma unroll
        for (int ks = 0; ks < 2; ks++) {
            const int k = ks * 8;
            uint32_t af[4][4];
#pragma unroll
            for (int mt = 0; mt < 4; mt++) {
                const uint32_t addr = sA0 + s * stageB +
                    ((uint32_t)(a_row_l + mt * 16) * SPAD + k + a_k_l) * 4;
                ldsm4(af[mt][0], af[mt][1], af[mt][2], af[mt][3], addr);
            }
            uint32_t bf[4][2];
#pragma unroll
            for (int np = 0; np < 2; np++) {
                const uint32_t addr = sB0 + s * stageB +
                    ((uint32_t)(b_row_l + np * 16) * SPAD + k + b_k_l) * 4;
                ldsm4(bf[np * 2][0], bf[np * 2][1], bf[np * 2 + 1][0], bf[np * 2 + 1][1], addr);
            }
#pragma unroll
            for (int mt = 0; mt < 4; mt++)
#pragma unroll
                for (int nt = 0; nt < 4; nt++)
                    asm volatile(
                        "mma.sync.aligned.m16n8k8.row.col.f32.tf32.tf32.f32 "
                        "{%0,%1,%2,%3},{%4,%5,%6,%7},{%8,%9},{%0,%1,%2,%3};"
                        : "+f"(acc[mt][nt][0]), "+f"(acc[mt][nt][1]),
                          "+f"(acc[mt][nt][2]), "+f"(acc[mt][nt][3])
                        : "r"(af[mt][0]), "r"(af[mt][1]), "r"(af[mt][2]), "r"(af[mt][3]),
                          "r"(bf[nt][0]), "r"(bf[nt][1]));
        }

        // issue load for iteration it+STAGES-1 into the stage freed last iter
        if (it + STAGES - 1 < NIT) {
            const int ls = (s + STAGES - 1 >= STAGES) ? (s - 1) : (s + STAGES - 1);
            const float* ap = aptr + (it + STAGES - 1) * BK;
            cp_async16(&As[ls][srow][scq],     ap);
            cp_async16(&As[ls][srow][scq + 4], ap + 4);
            const float* bp = bptr + (it + STAGES - 1) * BK;
            cp_async16(&Bs[ls][srow][scq],     bp);
            cp_async16(&Bs[ls][srow][scq + 4], bp + 4);
        }
        cp_commit();
        cp_wait2();
        __syncthreads();

        s = (s + 1 >= STAGES) ? 0 : (s + 1);
    }

    // ---------------- epilogue ----------------
#pragma unroll
    for (int mt = 0; mt < 4; mt++) {
        const int row0 = bm + warp_m * 64 + mt * 16 + (lane >> 2);
#pragma unroll
        for (int half = 0; half < 2; half++) {
            const int m = row0 + half * 8;
            int dst = 0;
            if (MODE == 1) dst = win_row_map(m);
#pragma unroll
            for (int nt = 0; nt < 4; nt++) {
                const int col0 = bn + warp_n * 32 + nt * 8 + 2 * (lane & 3);
#pragma unroll
                for (int j = 0; j < 2; j++) {
                    const int n = col0 + j;
                    const float v = acc[mt][nt][half * 2 + j] + bias[n];
                    if (MODE == 0) {
                        const int p  = n >> 9;      // 0=q,1=k,2=v
                        const int cc = n & 511;
                        g_qkv[(size_t)p * MTOT * CDIM + (size_t)m * CDIM + cc] = v;
                    } else {
                        out[(size_t)dst * CDIM + n] = v;
                    }
                }
            }
        }
    }
}

// ---------------- attention: per (window, token) 8x8 head-attention --------
__global__ void attn_kernel() {
    __shared__ float qs[4][512];
    __shared__ float ks[4][512];
    __shared__ float vs[4][512];
    __shared__ float ps[4][64];

    const int tid = threadIdx.x;
    const int u   = tid >> 6;
    const int lt  = tid & 63;
    const int unit = blockIdx.x * 4 + u;

    const size_t rowoff = (size_t)unit * CDIM;
    const float* qrow = g_qkv + rowoff;
    const float* krow = g_qkv + (size_t)MTOT * CDIM + rowoff;
    const float* vrow = g_qkv + 2ULL * MTOT * CDIM + rowoff;

#pragma unroll
    for (int i = lt; i < 512; i += 64) {
        qs[u][i] = qrow[i];
        ks[u][i] = krow[i];
        vs[u][i] = vrow[i];
    }
    __syncthreads();

    const int h = lt >> 3, g = lt & 7;
    float s = 0.f;
#pragma unroll
    for (int d = 0; d < 64; d++) s = fmaf(qs[u][h * 64 + d], ks[u][g * 64 + d], s);
    s *= 0.125f;

    float mx = s;
#pragma unroll
    for (int off = 4; off >= 1; off >>= 1)
        mx = fmaxf(mx, __shfl_xor_sync(0xffffffffu, mx, off));
    float e = __expf(s - mx);
    float sum = e;
#pragma unroll
    for (int off = 4; off >= 1; off >>= 1)
        sum += __shfl_xor_sync(0xffffffffu, sum, off);
    ps[u][lt] = e / sum;
    __syncthreads();

    const int w = unit / TTOK, t = unit - w * TTOK;
    float* obase = g_att + (size_t)w * (TTOK * CDIM) + (size_t)h * (TTOK * 64) + (size_t)t * 64;
    const int d0 = g * 8;
#pragma unroll
    for (int i = 0; i < 8; i++) {
        const int d = d0 + i;
        float o = 0.f;
#pragma unroll
        for (int gg = 0; gg < 8; gg++)
            o = fmaf(ps[u][h * 8 + gg], vs[u][gg * 64 + d], o);
        obase[d] = __uint_as_float(f2tf32(o));   // pre-round for proj GEMM
    }
}

// ---------------- launch ----------------
extern "C" void kernel_launch(void* const* d_in, const int* in_sizes, int n_in,
                              void* d_out, int out_size) {
    const float* x      = (const float*)d_in[0];
    const float* w_qkv  = (const float*)d_in[1];
    const float* b_qkv  = (const float*)d_in[2];
    const float* w_proj = (const float*)d_in[3];
    const float* b_proj = (const float*)d_in[4];
    float* out = (float*)d_out;

    // prep: rounded x, rounded+transposed weights
    {
        float* xr;  cudaGetSymbolAddress((void**)&xr,  g_xr);
        float* wqt; cudaGetSymbolAddress((void**)&wqt, g_wqt);
        float* wpt; cudaGetSymbolAddress((void**)&wpt, g_wpt);
        const size_t nx = (size_t)BATCH * HW * HW * CDIM;
        round_copy<<<(unsigned)(nx / 4 / 256), 256>>>(x, xr);
        {
            dim3 grid(NQKV / 32, CDIM / 32);
            round_transpose<<<grid, dim3(32, 8)>>>(w_qkv, wqt, CDIM, NQKV);
        }
        {
            dim3 grid(CDIM / 32, CDIM / 32);
            round_transpose<<<grid, dim3(32, 8)>>>(w_proj, wpt, CDIM, CDIM);
        }
    }
    {
        dim3 grid(NQKV / BN, MTOT / BM);   // 12 x 784 (N fast -> L2 reuse of A)
        mma_gemm<NQKV, 0><<<grid, 256>>>(b_qkv, nullptr);
    }
    {
        attn_kernel<<<MTOT / 4, 256>>>();
    }
    {
        dim3 grid(CDIM / BN, MTOT / BM);   // 4 x 784
        mma_gemm<CDIM, 1><<<grid, 256>>>(b_proj, out);
    }
}